// round 16
// baseline (speedup 1.0000x reference)
#include <cuda_runtime.h>
#include <cuda_bf16.h>
#include <math.h>
#include <stdint.h>

// Problem constants (fixed by setup_inputs)
#define NSPK 2048
#define MUTT 8
#define DEMB 512
#define NMROWS (NSPK * MUTT)   // 16384

// tcgen05 is sm_103a/sm_100a arch-SPECIFIC; gate on arch-feature macros so the
// family-portable compute_103 pass compiles the SIMT fallback instead.
#if defined(__CUDA_ARCH__) && \
    (defined(__CUDA_ARCH_FEAT_SM103_ALL) || defined(__CUDA_ARCH_FEAT_SM100_ALL) || \
     defined(__CUDA_ARCH_FEAT_SM101_ALL))
#define USE_TCGEN05 1
#else
#define USE_TCGEN05 0
#endif

// Scratch: bf16 normalized centroids, fp32 leave-one-out diagonal sims
__device__ __nv_bfloat16 g_cent_bf[NSPK * DEMB];
__device__ float g_diag[NMROWS];

// ===========================================================================
// PTX helpers
// ===========================================================================
__device__ __forceinline__ uint32_t smem_u32(const void* p) {
    uint32_t a;
    asm("{ .reg .u64 t; cvta.to.shared.u64 t, %1; cvt.u32.u64 %0, t; }"
        : "=r"(a) : "l"(p));
    return a;
}

#if USE_TCGEN05
__device__ __forceinline__ uint32_t elect_one() {
    uint32_t p;
    asm volatile("{\n\t.reg .pred p;\n\telect.sync _|p, 0xFFFFFFFF;\n\t"
                 "selp.b32 %0, 1, 0, p;\n\t}" : "=r"(p));
    return p;
}
__device__ __forceinline__ float ex2f(float x) {
    float r;
    asm("ex2.approx.f32 %0, %1;" : "=f"(r) : "f"(x));
    return r;
}

#define TCGEN05_ALLOC(smem_addr, nCols) \
    asm volatile("tcgen05.alloc.cta_group::1.sync.aligned.shared::cta.b32 [%0], %1;" \
                 :: "r"((uint32_t)(smem_addr)), "r"((uint32_t)(nCols)) : "memory")
#define TCGEN05_DEALLOC(tmem, nCols) \
    asm volatile("tcgen05.dealloc.cta_group::1.sync.aligned.b32 %0, %1;" \
                 :: "r"(tmem), "r"((uint32_t)(nCols)))
#define TCGEN05_RELINQUISH() \
    asm volatile("tcgen05.relinquish_alloc_permit.cta_group::1.sync.aligned;")
#define TCGEN05_WAIT_ST() asm volatile("tcgen05.wait::st.sync.aligned;" ::: "memory")
#define TCGEN05_WAIT_LD() asm volatile("tcgen05.wait::ld.sync.aligned;" ::: "memory")
#define TCGEN05_FENCE_BEFORE() asm volatile("tcgen05.fence::before_thread_sync;" ::: "memory")
#define TCGEN05_FENCE_AFTER()  asm volatile("tcgen05.fence::after_thread_sync;" ::: "memory")
#define FENCE_PROXY_ASYNC() asm volatile("fence.proxy.async.shared::cta;" ::: "memory")
#define TCGEN05_COMMIT(mbar) \
    asm volatile("tcgen05.commit.cta_group::1.mbarrier::arrive::one.shared::cluster.b64 [%0];" \
                 :: "r"((uint32_t)(mbar)) : "memory")
#define MBARRIER_INIT(mbar, cnt) \
    asm volatile("mbarrier.init.shared.b64 [%0], %1;" \
                 :: "r"((uint32_t)(mbar)), "r"((uint32_t)(cnt)) : "memory")
#define MBARRIER_INVAL(mbar) \
    asm volatile("mbarrier.inval.shared.b64 [%0];" :: "r"((uint32_t)(mbar)) : "memory")

#define MBARRIER_WAIT_PARITY(mbar, parity) do {                                   \
    uint32_t _m = (uint32_t)(mbar); uint32_t _p = (uint32_t)(parity);             \
    asm volatile(                                                                 \
        "{\n\t.reg .pred P1;\n\t"                                                 \
        "WAIT_LOOP_%=:\n\t"                                                       \
        "mbarrier.try_wait.parity.acquire.cta.shared::cta.b64 P1, [%0], %1, 0x989680;\n\t" \
        "@P1 bra.uni WAIT_DONE_%=;\n\t"                                           \
        "bra.uni WAIT_LOOP_%=;\n\t"                                               \
        "WAIT_DONE_%=:\n\t}"                                                      \
        :: "r"(_m), "r"(_p) : "memory");                                          \
} while (0)

#define TCGEN05_MMA_F16(d_tmem, a_tmem, b_desc, idesc, enable_d) do {             \
    uint32_t _en = (enable_d) ? 1u : 0u; uint32_t _z = 0u;                        \
    asm volatile(                                                                 \
        "{\n\t.reg .pred p;\n\tsetp.ne.u32 p, %6, 0;\n\t"                         \
        "tcgen05.mma.cta_group::1.kind::f16 [%0], [%1], %2, %3, "                 \
        "{%4, %4, %4, %4}, p;\n\t}"                                               \
        :: "r"(d_tmem), "r"(a_tmem), "l"(b_desc), "r"(idesc),                     \
           "r"(_z), "r"(_z), "r"(_en) : "memory");                                \
} while (0)

#define TCGEN05_ST_X64(tmem_addr, r)                                              \
    asm volatile("tcgen05.st.sync.aligned.32x32b.x64.b32 [%0], "                  \
        "{%1, %2, %3, %4, %5, %6, %7, %8, "                                       \
        " %9, %10, %11, %12, %13, %14, %15, %16, "                                \
        " %17, %18, %19, %20, %21, %22, %23, %24, "                               \
        " %25, %26, %27, %28, %29, %30, %31, %32, "                               \
        " %33, %34, %35, %36, %37, %38, %39, %40, "                               \
        " %41, %42, %43, %44, %45, %46, %47, %48, "                               \
        " %49, %50, %51, %52, %53, %54, %55, %56, "                               \
        " %57, %58, %59, %60, %61, %62, %63, %64};"                               \
        :: "r"(tmem_addr),                                                        \
           "r"((r)[0]),  "r"((r)[1]),  "r"((r)[2]),  "r"((r)[3]),                 \
           "r"((r)[4]),  "r"((r)[5]),  "r"((r)[6]),  "r"((r)[7]),                 \
           "r"((r)[8]),  "r"((r)[9]),  "r"((r)[10]), "r"((r)[11]),                \
           "r"((r)[12]), "r"((r)[13]), "r"((r)[14]), "r"((r)[15]),                \
           "r"((r)[16]), "r"((r)[17]), "r"((r)[18]), "r"((r)[19]),                \
           "r"((r)[20]), "r"((r)[21]), "r"((r)[22]), "r"((r)[23]),                \
           "r"((r)[24]), "r"((r)[25]), "r"((r)[26]), "r"((r)[27]),                \
           "r"((r)[28]), "r"((r)[29]), "r"((r)[30]), "r"((r)[31]),                \
           "r"((r)[32]), "r"((r)[33]), "r"((r)[34]), "r"((r)[35]),                \
           "r"((r)[36]), "r"((r)[37]), "r"((r)[38]), "r"((r)[39]),                \
           "r"((r)[40]), "r"((r)[41]), "r"((r)[42]), "r"((r)[43]),                \
           "r"((r)[44]), "r"((r)[45]), "r"((r)[46]), "r"((r)[47]),                \
           "r"((r)[48]), "r"((r)[49]), "r"((r)[50]), "r"((r)[51]),                \
           "r"((r)[52]), "r"((r)[53]), "r"((r)[54]), "r"((r)[55]),                \
           "r"((r)[56]), "r"((r)[57]), "r"((r)[58]), "r"((r)[59]),                \
           "r"((r)[60]), "r"((r)[61]), "r"((r)[62]), "r"((r)[63])                 \
        : "memory")

#define TCGEN05_LD_X32(r, tmem_addr)                                              \
    asm volatile("tcgen05.ld.sync.aligned.32x32b.x32.b32 "                        \
        "{%0, %1, %2, %3, %4, %5, %6, %7, "                                       \
        " %8, %9, %10, %11, %12, %13, %14, %15, "                                 \
        " %16, %17, %18, %19, %20, %21, %22, %23, "                               \
        " %24, %25, %26, %27, %28, %29, %30, %31}, [%32];"                        \
        : "=r"((r)[0]),  "=r"((r)[1]),  "=r"((r)[2]),  "=r"((r)[3]),              \
          "=r"((r)[4]),  "=r"((r)[5]),  "=r"((r)[6]),  "=r"((r)[7]),              \
          "=r"((r)[8]),  "=r"((r)[9]),  "=r"((r)[10]), "=r"((r)[11]),             \
          "=r"((r)[12]), "=r"((r)[13]), "=r"((r)[14]), "=r"((r)[15]),             \
          "=r"((r)[16]), "=r"((r)[17]), "=r"((r)[18]), "=r"((r)[19]),             \
          "=r"((r)[20]), "=r"((r)[21]), "=r"((r)[22]), "=r"((r)[23]),             \
          "=r"((r)[24]), "=r"((r)[25]), "=r"((r)[26]), "=r"((r)[27]),             \
          "=r"((r)[28]), "=r"((r)[29]), "=r"((r)[30]), "=r"((r)[31])              \
        : "r"(tmem_addr))

// SMEM descriptor: SW128, version 1, SBO=64 (1024B per 8-row group), LBO=1
#define SMEM_DESC_BASE ((2ull << 61) | (1ull << 46) | (64ull << 32) | (1ull << 16))
#endif  // USE_TCGEN05

// ===========================================================================
// Kernel 1: centroids (bf16 out) + exact fp32 leave-one-out diag. Warp/speaker.
// ===========================================================================
__global__ void __launch_bounds__(256) centroid_kernel(const float* __restrict__ E,
                                                       float* __restrict__ out) {
    if (blockIdx.x == 0 && threadIdx.x == 0) out[0] = 0.0f;

    int warp = (blockIdx.x * blockDim.x + threadIdx.x) >> 5;
    int lane = threadIdx.x & 31;
    if (warp >= NSPK) return;

    const float* e = E + (size_t)warp * (MUTT * DEMB);

    float4 s[4];
#pragma unroll
    for (int c = 0; c < 4; c++) s[c] = make_float4(0.f, 0.f, 0.f, 0.f);

    float q[MUTT];
#pragma unroll
    for (int m = 0; m < MUTT; m++) {
        q[m] = 0.f;
#pragma unroll
        for (int c = 0; c < 4; c++) {
            float4 v = *(const float4*)(e + m * DEMB + c * 128 + lane * 4);
            s[c].x += v.x; s[c].y += v.y; s[c].z += v.z; s[c].w += v.w;
            q[m] += v.x * v.x + v.y * v.y + v.z * v.z + v.w * v.w;
        }
    }
    float p[MUTT];
#pragma unroll
    for (int m = 0; m < MUTT; m++) {
        p[m] = 0.f;
#pragma unroll
        for (int c = 0; c < 4; c++) {
            float4 v = *(const float4*)(e + m * DEMB + c * 128 + lane * 4);
            p[m] += v.x * s[c].x + v.y * s[c].y + v.z * s[c].z + v.w * s[c].w;
        }
    }
    float ns = 0.f;
#pragma unroll
    for (int c = 0; c < 4; c++)
        ns += s[c].x * s[c].x + s[c].y * s[c].y + s[c].z * s[c].z + s[c].w * s[c].w;

#pragma unroll
    for (int off = 16; off > 0; off >>= 1) {
#pragma unroll
        for (int m = 0; m < MUTT; m++) {
            p[m] += __shfl_xor_sync(0xffffffffu, p[m], off);
            q[m] += __shfl_xor_sync(0xffffffffu, q[m], off);
        }
        ns += __shfl_xor_sync(0xffffffffu, ns, off);
    }

    float inv = rsqrtf(ns);
#pragma unroll
    for (int c = 0; c < 4; c++) {
        __nv_bfloat162 h0 = __float22bfloat162_rn(make_float2(s[c].x * inv, s[c].y * inv));
        __nv_bfloat162 h1 = __float22bfloat162_rn(make_float2(s[c].z * inv, s[c].w * inv));
        uint32_t u0 = *(uint32_t*)&h0, u1 = *(uint32_t*)&h1;
        *(uint2*)(g_cent_bf + (size_t)warp * DEMB + c * 128 + lane * 4) = make_uint2(u0, u1);
    }
    if (lane < MUTT) {
        float pm = p[lane], qm = q[lane];
        g_diag[warp * MUTT + lane] = (pm - qm) * rsqrtf(ns - 2.f * pm + qm);
    }
}

// ===========================================================================
// Kernel 2 (grid 128, block 416, dynamic smem)
//   sm_103a: warp-specialized tcgen05 pipeline, N-chunk = 128 (16 chunks)
//   to amortize per-chunk sync/fence fixed costs. K is split into 2 halves of
//   256 so B streams as 64 KB half-buffers (3-deep ring).
//     warps 0-7  : pure epilogue consumers (64 cols/thread per chunk)
//     warps 8-11 : B half-chunk loaders
//     warp 12    : MMA issuer (16+16 MMAs per chunk, one commit)
//   TMEM: A = [0,256), D0 = [256,384), D1 = [384,512)  (exactly 512 cols)
//   Barriers:
//     mbar ring of 4   : mma_done(chunk) (consumers wait c, loaders c-1/c-2)
//     named 3/4/5 (160): B half-buffer ready, loaders arrive / issuer syncs
//     named 6/7   (288): D[c&1] free, consumers arrive / issuer syncs
//     named 8     (288): A-in-TMEM;  named 2 (256): consumer reductions
// ===========================================================================
#define BROWS 128
#define NB 128
#define NCHUNK (NSPK / NB)     // 16
#define NHALF (NCHUNK * 2)     // 32 half-chunks
#define KHALF 256              // k elems per half
#define KSTEPS_H 16            // 16-elem k-steps per half
#define NBUF 3
#define HBUF_BYTES 65536       // 128 rows x 256 bf16 = 64 KB
#define MMA_IDESC 0x8200490u   // f32 acc, bf16 A/B, K-major, M=128, N=128
#define NTHREADS 416
#define LOG2E 1.4426950408889634f

// shared memory offsets
#define SM_TMEMPTR 0
#define SM_MBAR0   8                      // 4 mbarriers: 8..40
#define SM_BUF0    2048
#define SM_RED     (2048 + NBUF * HBUF_BYTES)  // 256 floats
#define SM_WS      (SM_RED + 1024)        // 4 floats
#define SMEM_TOTAL (SM_WS + 64)

// TMEM columns
#define TM_A  0
#define TM_D0 256

__global__ void __launch_bounds__(NTHREADS, 1) gemm_loss_kernel(const float* __restrict__ E,
                                                                const float* __restrict__ wp,
                                                                const float* __restrict__ bp,
                                                                float* __restrict__ out) {
    extern __shared__ char smem[];
#if USE_TCGEN05
    uint32_t smem_base = smem_u32(smem);
    int tid = threadIdx.x;
    int wid = tid >> 5;
    int lane = tid & 31;
    int r0 = blockIdx.x * BROWS;

    if (wid == 0) TCGEN05_ALLOC(smem_base + SM_TMEMPTR, 512);
    if (tid == 0) {
#pragma unroll
        for (int i = 0; i < 4; i++) MBARRIER_INIT(smem_base + SM_MBAR0 + 8 * i, 1);
    }
    __syncthreads();
    uint32_t tmem_base;
    asm volatile("ld.shared.b32 %0, [%1];" : "=r"(tmem_base) : "r"(smem_base + SM_TMEMPTR));

    if (wid >= 8 && wid < 12) {
        // ------------- loader warps (8-11): stream B half-chunks -------------
        int ltid = tid - 256;
        int bufidx = 0;
#pragma unroll 1
        for (int H = 0; H < NHALF; H++) {
            int c = H >> 1, h = H & 1;
            if (H >= NBUF) {
                // buffer reused from half H-NBUF -> freed when its chunk's MMA done
                int pchunk = (H - NBUF) >> 1;
                MBARRIER_WAIT_PARITY(smem_base + SM_MBAR0 + 8 * (pchunk & 3),
                                     (pchunk >> 2) & 1);
            }
            const __nv_bfloat16* gsrc = g_cent_bf + (size_t)c * NB * DEMB + h * KHALF;
            char* buf = smem + SM_BUF0 + bufidx * HBUF_BYTES;
#pragma unroll
            for (int i = 0; i < 32; i++) {
                int lin = ltid + i * 128;            // uint4 idx, 0..4095
                int brow = lin >> 5;                 // centroid row in chunk, 0..127
                int kc = (lin & 31) << 3;            // k-col within half, mult of 8
                uint4 v = *(const uint4*)(gsrc + (size_t)brow * DEMB + kc);
                // blocked SW128 atoms: 8 rows x 64 bf16; 16 atom-rows per atom-col
                uint32_t off = (uint32_t)((brow >> 3) + ((kc >> 6) << 4)) * 1024u
                             + (uint32_t)(brow & 7) * 128u + (uint32_t)(kc & 63) * 2u;
                off ^= ((off >> 3) & 0x70u);         // SW128 swizzle
                *(uint4*)(buf + off) = v;
            }
            FENCE_PROXY_ASYNC();
            {
                int barid = 3 + bufidx;
                asm volatile("bar.arrive %0, 160;" :: "r"(barid) : "memory");
            }
            bufidx = (bufidx + 1 == NBUF) ? 0 : bufidx + 1;
        }
    } else if (wid == 12) {
        // ------------------------ MMA issuer warp (12) ------------------------
        asm volatile("bar.sync 8, 288;" ::: "memory");  // A in TMEM
        TCGEN05_FENCE_AFTER();
#pragma unroll 1
        for (int c = 0; c < NCHUNK; c++) {
            int bufA = (2 * c) % NBUF;
            int bufB = (2 * c + 1) % NBUF;
            {   // first K-half ready
                int barid = 3 + bufA;
                asm volatile("bar.sync %0, 160;" :: "r"(barid) : "memory");
            }
            if (c >= 2) {   // D[c&1] free (epi(c-2) done)
                int barid = 6 + (c & 1);
                asm volatile("bar.sync %0, 288;" :: "r"(barid) : "memory");
            }
            uint32_t dt = tmem_base + TM_D0 + (c & 1) * 128;
            if (elect_one()) {
                uint64_t bdesc = SMEM_DESC_BASE |
                    (((uint64_t)(smem_base + SM_BUF0 + bufA * HBUF_BYTES) >> 4) & 0x3FFF);
#pragma unroll
                for (int s = 0; s < KSTEPS_H; s++) {
                    uint64_t bd = bdesc + (uint64_t)(((s >> 2) << 10) + ((s & 3) << 1));
                    TCGEN05_MMA_F16(dt, tmem_base + TM_A + s * 8, bd, MMA_IDESC, s > 0);
                }
            }
            {   // second K-half ready
                int barid = 3 + bufB;
                asm volatile("bar.sync %0, 160;" :: "r"(barid) : "memory");
            }
            if (elect_one()) {
                uint64_t bdesc = SMEM_DESC_BASE |
                    (((uint64_t)(smem_base + SM_BUF0 + bufB * HBUF_BYTES) >> 4) & 0x3FFF);
#pragma unroll
                for (int s = 0; s < KSTEPS_H; s++) {
                    uint64_t bd = bdesc + (uint64_t)(((s >> 2) << 10) + ((s & 3) << 1));
                    TCGEN05_MMA_F16(dt, tmem_base + TM_A + 128 + s * 8, bd, MMA_IDESC, true);
                }
                TCGEN05_COMMIT(smem_base + SM_MBAR0 + 8 * (c & 3));
            }
        }
    } else {
        // ---------------- consumer warps (0-7): pure epilogue ----------------
        // Prologue: A (f32 -> bf16) into TMEM, threads 0-127 own one row each
        if (tid < 128) {
            const float* arow = E + (size_t)(r0 + tid) * DEMB;
            uint32_t warp_off = (uint32_t)(tid >> 5) << 21;
#pragma unroll 1
            for (int bt = 0; bt < 4; bt++) {
                uint32_t regs[64];
#pragma unroll
                for (int i = 0; i < 32; i++) {
                    float4 v = ((const float4*)(arow + bt * 128))[i];
                    __nv_bfloat162 h0 = __float22bfloat162_rn(make_float2(v.x, v.y));
                    __nv_bfloat162 h1 = __float22bfloat162_rn(make_float2(v.z, v.w));
                    regs[2 * i]     = *(uint32_t*)&h0;
                    regs[2 * i + 1] = *(uint32_t*)&h1;
                }
                TCGEN05_ST_X64(tmem_base + TM_A + bt * 64 + warp_off, regs);
            }
            TCGEN05_WAIT_ST();
        }
        TCGEN05_FENCE_BEFORE();
        asm volatile("bar.arrive 8, 288;" ::: "memory");  // A ready -> issuer

        float wabs = fabsf(wp[0]);
        float bb = bp[0];
        float wl = wabs * LOG2E;
        float bl = bb * LOG2E;
        int half = wid >> 2;                   // 0: cols 0-63, 1: cols 64-127
        int myrow = ((wid & 3) << 5) + lane;   // TMEM lane = A-tile row
        int grow = r0 + myrow;
        int spk = grow >> 3;                   // own-speaker column (M=8)
        float dval = fmaf(wabs, g_diag[grow], bb);   // exact, natural-log domain
        float dval_l = dval * LOG2E;
        float e_dval = ex2f(dval_l);
        float ssum = 0.f;

#pragma unroll 1
        for (int c = 0; c < NCHUNK; c++) {
            MBARRIER_WAIT_PARITY(smem_base + SM_MBAR0 + 8 * (c & 3), (c >> 2) & 1);
            TCGEN05_FENCE_AFTER();
            uint32_t dbase = tmem_base + TM_D0 + (c & 1) * 128 + half * 64;
            int colbase = c * NB + half * 64;
            float s0 = 0.f, s1 = 0.f;
            int dsel = spk - colbase;          // own column if in [0,64)
#pragma unroll 1
            for (int g = 0; g < 2; g++) {
                uint32_t d[32];
                TCGEN05_LD_X32(d, dbase + g * 32);
                TCGEN05_WAIT_LD();
#pragma unroll
                for (int j = 0; j < 32; j += 2) {
                    s0 += ex2f(fmaf(wl, __uint_as_float(d[j]), bl));
                    s1 += ex2f(fmaf(wl, __uint_as_float(d[j + 1]), bl));
                }
                int ds = dsel - g * 32;
                if (ds >= 0 && ds < 32) {      // replace own column by exact diag
                    s0 += e_dval - ex2f(fmaf(wl, __uint_as_float(d[ds]), bl));
                }
            }
            ssum += s0 + s1;
            TCGEN05_FENCE_BEFORE();
            {   // D[c&1] free -> issuer may reuse for chunk c+2
                int barid = 6 + (c & 1);
                asm volatile("bar.arrive %0, 288;" :: "r"(barid) : "memory");
            }
        }

        // combine halves, per-row loss, block reduce (consumer-only barrier 2)
        float* red = (float*)(smem + SM_RED);
        red[half * 128 + myrow] = ssum;
        asm volatile("bar.sync 2, 256;" ::: "memory");

        if (wid < 4) {
            float total = red[myrow] + red[128 + myrow];
            float lr = logf(total) - dval;          // logsumexp - own logit
#pragma unroll
            for (int off = 16; off > 0; off >>= 1)
                lr += __shfl_xor_sync(0xffffffffu, lr, off);
            if (lane == 0) ((float*)(smem + SM_WS))[wid] = lr;
        }
        asm volatile("bar.sync 2, 256;" ::: "memory");
        if (tid == 0) {
            float* ws = (float*)(smem + SM_WS);
            atomicAdd(out, (ws[0] + ws[1] + ws[2] + ws[3]) * (1.0f / (float)NMROWS));
        }
    }

    // full-CTA teardown
    __syncthreads();
    if (tid == 0) {
#pragma unroll
        for (int i = 0; i < 4; i++) MBARRIER_INVAL(smem_base + SM_MBAR0 + 8 * i);
    }
    __syncthreads();
    if (wid == 0) {
        TCGEN05_RELINQUISH();
        TCGEN05_DEALLOC(tmem_base, 512);
    }
#else
    // ---------------- portable SIMT fallback (compile-only on GB300) ----------
    float (*As)[132] = (float (*)[132])(smem);                 // [16][132]
    float (*Bs)[132] = (float (*)[132])(smem + 16 * 132 * 4);  // [16][132]
    float* red = (float*)(smem + 2 * 16 * 132 * 4);            // [16]

    int tid = threadIdx.x;
    int tx = tid & 15;
    int ty = tid >> 4;
    int r0 = blockIdx.x * BROWS;
    int rowbase = r0 + ty * 8;
    bool active = tid < 256;

    float wabs = fabsf(wp[0]);
    float bb = bp[0];

    float dval[8];
#pragma unroll
    for (int i = 0; i < 8; i++)
        dval[i] = active ? fmaf(wabs, g_diag[rowbase + i], bb) : 0.f;

    float mrun[8], srun[8];
#pragma unroll
    for (int i = 0; i < 8; i++) { mrun[i] = -1e30f; srun[i] = 0.f; }

    for (int c0 = 0; c0 < NSPK; c0 += 128) {
        float acc[8][8];
#pragma unroll
        for (int i = 0; i < 8; i++)
#pragma unroll
            for (int j = 0; j < 8; j++) acc[i][j] = 0.f;

        for (int k0 = 0; k0 < DEMB; k0 += 16) {
            for (int i4 = tid; i4 < 512; i4 += NTHREADS) {
                int row = i4 >> 2;
                int c4 = i4 & 3;
                float4 va = *(const float4*)(E + (size_t)(r0 + row) * DEMB + k0 + c4 * 4);
                As[c4 * 4 + 0][row] = va.x;
                As[c4 * 4 + 1][row] = va.y;
                As[c4 * 4 + 2][row] = va.z;
                As[c4 * 4 + 3][row] = va.w;
                uint2 ub = *(const uint2*)(g_cent_bf + (size_t)(c0 + row) * DEMB + k0 + c4 * 4);
                __nv_bfloat162 b0 = *(__nv_bfloat162*)&ub.x;
                __nv_bfloat162 b1 = *(__nv_bfloat162*)&ub.y;
                float2 f0 = __bfloat1622float2(b0);
                float2 f1 = __bfloat1622float2(b1);
                Bs[c4 * 4 + 0][row] = f0.x;
                Bs[c4 * 4 + 1][row] = f0.y;
                Bs[c4 * 4 + 2][row] = f1.x;
                Bs[c4 * 4 + 3][row] = f1.y;
            }
            __syncthreads();

            if (active) {
#pragma unroll
                for (int kk = 0; kk < 16; kk++) {
                    float4 a0 = *(const float4*)(&As[kk][ty * 8]);
                    float4 a1 = *(const float4*)(&As[kk][ty * 8 + 4]);
                    float4 b0 = *(const float4*)(&Bs[kk][tx * 8]);
                    float4 b1 = *(const float4*)(&Bs[kk][tx * 8 + 4]);
                    float av[8] = {a0.x, a0.y, a0.z, a0.w, a1.x, a1.y, a1.z, a1.w};
                    float bv[8] = {b0.x, b0.y, b0.z, b0.w, b1.x, b1.y, b1.z, b1.w};
#pragma unroll
                    for (int i = 0; i < 8; i++)
#pragma unroll
                        for (int j = 0; j < 8; j++) acc[i][j] = fmaf(av[i], bv[j], acc[i][j]);
                }
            }
            __syncthreads();
        }

        if (active) {
            int colbase = c0 + tx * 8;
#pragma unroll
            for (int i = 0; i < 8; i++) {
                int spk = (rowbase + i) >> 3;
                float z[8];
#pragma unroll
                for (int j = 0; j < 8; j++) z[j] = fmaf(wabs, acc[i][j], bb);
                int dcol = spk - colbase;
                if (dcol >= 0 && dcol < 8) z[dcol] = dval[i];

                float tm = z[0];
#pragma unroll
                for (int j = 1; j < 8; j++) tm = fmaxf(tm, z[j]);
#pragma unroll
                for (int off = 8; off > 0; off >>= 1)
                    tm = fmaxf(tm, __shfl_xor_sync(0xffffffffu, tm, off));

                float nm = fmaxf(mrun[i], tm);
                float ts = 0.f;
#pragma unroll
                for (int j = 0; j < 8; j++) ts += __expf(z[j] - nm);
#pragma unroll
                for (int off = 8; off > 0; off >>= 1)
                    ts += __shfl_xor_sync(0xffffffffu, ts, off);

                srun[i] = srun[i] * __expf(mrun[i] - nm) + ts;
                mrun[i] = nm;
            }
        }
    }

    if (active && tx == 0) {
        float lsum = 0.f;
#pragma unroll
        for (int i = 0; i < 8; i++) lsum += logf(srun[i]) + mrun[i] - dval[i];
        red[ty] = lsum;
    }
    __syncthreads();
    if (tid == 0) {
        float t = 0.f;
#pragma unroll
        for (int k = 0; k < 16; k++) t += red[k];
        atomicAdd(out, t * (1.0f / (float)NMROWS));
    }
#endif
}

// ===========================================================================
extern "C" void kernel_launch(void* const* d_in, const int* in_sizes, int n_in,
                              void* d_out, int out_size) {
    const float* E = (const float*)d_in[0];
    const float* w = (const float*)d_in[1];
    const float* b = (const float*)d_in[2];
    float* out = (float*)d_out;

    cudaFuncSetAttribute(gemm_loss_kernel,
                         cudaFuncAttributeMaxDynamicSharedMemorySize, SMEM_TOTAL);

    centroid_kernel<<<256, 256>>>(E, out);
    gemm_loss_kernel<<<NMROWS / BROWS, NTHREADS, SMEM_TOTAL>>>(E, w, b, out);
}

// round 17
// speedup vs baseline: 1.6605x; 1.6605x over previous
#include <cuda_runtime.h>
#include <cuda_bf16.h>
#include <math.h>
#include <stdint.h>

// Problem constants (fixed by setup_inputs)
#define NSPK 2048
#define MUTT 8
#define DEMB 512
#define NMROWS (NSPK * MUTT)   // 16384

// tcgen05 is sm_103a/sm_100a arch-SPECIFIC; gate on arch-feature macros so the
// family-portable compute_103 pass compiles the SIMT fallback instead.
#if defined(__CUDA_ARCH__) && \
    (defined(__CUDA_ARCH_FEAT_SM103_ALL) || defined(__CUDA_ARCH_FEAT_SM100_ALL) || \
     defined(__CUDA_ARCH_FEAT_SM101_ALL))
#define USE_TCGEN05 1
#else
#define USE_TCGEN05 0
#endif

// Scratch: bf16 normalized centroids, fp32 leave-one-out diagonal sims
__device__ __nv_bfloat16 g_cent_bf[NSPK * DEMB];
__device__ float g_diag[NMROWS];

// ===========================================================================
// PTX helpers
// ===========================================================================
__device__ __forceinline__ uint32_t smem_u32(const void* p) {
    uint32_t a;
    asm("{ .reg .u64 t; cvta.to.shared.u64 t, %1; cvt.u32.u64 %0, t; }"
        : "=r"(a) : "l"(p));
    return a;
}

#if USE_TCGEN05
__device__ __forceinline__ uint32_t elect_one() {
    uint32_t p;
    asm volatile("{\n\t.reg .pred p;\n\telect.sync _|p, 0xFFFFFFFF;\n\t"
                 "selp.b32 %0, 1, 0, p;\n\t}" : "=r"(p));
    return p;
}
__device__ __forceinline__ float ex2f(float x) {
    float r;
    asm("ex2.approx.f32 %0, %1;" : "=f"(r) : "f"(x));
    return r;
}

#define TCGEN05_ALLOC(smem_addr, nCols) \
    asm volatile("tcgen05.alloc.cta_group::1.sync.aligned.shared::cta.b32 [%0], %1;" \
                 :: "r"((uint32_t)(smem_addr)), "r"((uint32_t)(nCols)) : "memory")
#define TCGEN05_DEALLOC(tmem, nCols) \
    asm volatile("tcgen05.dealloc.cta_group::1.sync.aligned.b32 %0, %1;" \
                 :: "r"(tmem), "r"((uint32_t)(nCols)))
#define TCGEN05_RELINQUISH() \
    asm volatile("tcgen05.relinquish_alloc_permit.cta_group::1.sync.aligned;")
#define TCGEN05_WAIT_ST() asm volatile("tcgen05.wait::st.sync.aligned;" ::: "memory")
#define TCGEN05_WAIT_LD() asm volatile("tcgen05.wait::ld.sync.aligned;" ::: "memory")
#define TCGEN05_FENCE_BEFORE() asm volatile("tcgen05.fence::before_thread_sync;" ::: "memory")
#define TCGEN05_FENCE_AFTER()  asm volatile("tcgen05.fence::after_thread_sync;" ::: "memory")
#define FENCE_PROXY_ASYNC() asm volatile("fence.proxy.async.shared::cta;" ::: "memory")
#define TCGEN05_COMMIT(mbar) \
    asm volatile("tcgen05.commit.cta_group::1.mbarrier::arrive::one.shared::cluster.b64 [%0];" \
                 :: "r"((uint32_t)(mbar)) : "memory")
#define MBARRIER_INIT(mbar, cnt) \
    asm volatile("mbarrier.init.shared.b64 [%0], %1;" \
                 :: "r"((uint32_t)(mbar)), "r"((uint32_t)(cnt)) : "memory")
#define MBARRIER_INVAL(mbar) \
    asm volatile("mbarrier.inval.shared.b64 [%0];" :: "r"((uint32_t)(mbar)) : "memory")

#define MBARRIER_WAIT_PARITY(mbar, parity) do {                                   \
    uint32_t _m = (uint32_t)(mbar); uint32_t _p = (uint32_t)(parity);             \
    asm volatile(                                                                 \
        "{\n\t.reg .pred P1;\n\t"                                                 \
        "WAIT_LOOP_%=:\n\t"                                                       \
        "mbarrier.try_wait.parity.acquire.cta.shared::cta.b64 P1, [%0], %1, 0x989680;\n\t" \
        "@P1 bra.uni WAIT_DONE_%=;\n\t"                                           \
        "bra.uni WAIT_LOOP_%=;\n\t"                                               \
        "WAIT_DONE_%=:\n\t}"                                                      \
        :: "r"(_m), "r"(_p) : "memory");                                          \
} while (0)

#define TCGEN05_MMA_F16(d_tmem, a_tmem, b_desc, idesc, enable_d) do {             \
    uint32_t _en = (enable_d) ? 1u : 0u; uint32_t _z = 0u;                        \
    asm volatile(                                                                 \
        "{\n\t.reg .pred p;\n\tsetp.ne.u32 p, %6, 0;\n\t"                         \
        "tcgen05.mma.cta_group::1.kind::f16 [%0], [%1], %2, %3, "                 \
        "{%4, %4, %4, %4}, p;\n\t}"                                               \
        :: "r"(d_tmem), "r"(a_tmem), "l"(b_desc), "r"(idesc),                     \
           "r"(_z), "r"(_z), "r"(_en) : "memory");                                \
} while (0)

#define CP_ASYNC_16(dst_smem, src_gptr) \
    asm volatile("cp.async.cg.shared.global [%0], [%1], 16;" \
                 :: "r"((uint32_t)(dst_smem)), "l"(src_gptr) : "memory")
#define CP_ASYNC_COMMIT() asm volatile("cp.async.commit_group;" ::: "memory")
#define CP_ASYNC_WAIT_ALL() asm volatile("cp.async.wait_group 0;" ::: "memory")

#define TCGEN05_ST_X64(tmem_addr, r)                                              \
    asm volatile("tcgen05.st.sync.aligned.32x32b.x64.b32 [%0], "                  \
        "{%1, %2, %3, %4, %5, %6, %7, %8, "                                       \
        " %9, %10, %11, %12, %13, %14, %15, %16, "                                \
        " %17, %18, %19, %20, %21, %22, %23, %24, "                               \
        " %25, %26, %27, %28, %29, %30, %31, %32, "                               \
        " %33, %34, %35, %36, %37, %38, %39, %40, "                               \
        " %41, %42, %43, %44, %45, %46, %47, %48, "                               \
        " %49, %50, %51, %52, %53, %54, %55, %56, "                               \
        " %57, %58, %59, %60, %61, %62, %63, %64};"                               \
        :: "r"(tmem_addr),                                                        \
           "r"((r)[0]),  "r"((r)[1]),  "r"((r)[2]),  "r"((r)[3]),                 \
           "r"((r)[4]),  "r"((r)[5]),  "r"((r)[6]),  "r"((r)[7]),                 \
           "r"((r)[8]),  "r"((r)[9]),  "r"((r)[10]), "r"((r)[11]),                \
           "r"((r)[12]), "r"((r)[13]), "r"((r)[14]), "r"((r)[15]),                \
           "r"((r)[16]), "r"((r)[17]), "r"((r)[18]), "r"((r)[19]),                \
           "r"((r)[20]), "r"((r)[21]), "r"((r)[22]), "r"((r)[23]),                \
           "r"((r)[24]), "r"((r)[25]), "r"((r)[26]), "r"((r)[27]),                \
           "r"((r)[28]), "r"((r)[29]), "r"((r)[30]), "r"((r)[31]),                \
           "r"((r)[32]), "r"((r)[33]), "r"((r)[34]), "r"((r)[35]),                \
           "r"((r)[36]), "r"((r)[37]), "r"((r)[38]), "r"((r)[39]),                \
           "r"((r)[40]), "r"((r)[41]), "r"((r)[42]), "r"((r)[43]),                \
           "r"((r)[44]), "r"((r)[45]), "r"((r)[46]), "r"((r)[47]),                \
           "r"((r)[48]), "r"((r)[49]), "r"((r)[50]), "r"((r)[51]),                \
           "r"((r)[52]), "r"((r)[53]), "r"((r)[54]), "r"((r)[55]),                \
           "r"((r)[56]), "r"((r)[57]), "r"((r)[58]), "r"((r)[59]),                \
           "r"((r)[60]), "r"((r)[61]), "r"((r)[62]), "r"((r)[63])                 \
        : "memory")

#define TCGEN05_LD_X32(r, tmem_addr)                                              \
    asm volatile("tcgen05.ld.sync.aligned.32x32b.x32.b32 "                        \
        "{%0, %1, %2, %3, %4, %5, %6, %7, "                                       \
        " %8, %9, %10, %11, %12, %13, %14, %15, "                                 \
        " %16, %17, %18, %19, %20, %21, %22, %23, "                               \
        " %24, %25, %26, %27, %28, %29, %30, %31}, [%32];"                        \
        : "=r"((r)[0]),  "=r"((r)[1]),  "=r"((r)[2]),  "=r"((r)[3]),              \
          "=r"((r)[4]),  "=r"((r)[5]),  "=r"((r)[6]),  "=r"((r)[7]),              \
          "=r"((r)[8]),  "=r"((r)[9]),  "=r"((r)[10]), "=r"((r)[11]),             \
          "=r"((r)[12]), "=r"((r)[13]), "=r"((r)[14]), "=r"((r)[15]),             \
          "=r"((r)[16]), "=r"((r)[17]), "=r"((r)[18]), "=r"((r)[19]),             \
          "=r"((r)[20]), "=r"((r)[21]), "=r"((r)[22]), "=r"((r)[23]),             \
          "=r"((r)[24]), "=r"((r)[25]), "=r"((r)[26]), "=r"((r)[27]),             \
          "=r"((r)[28]), "=r"((r)[29]), "=r"((r)[30]), "=r"((r)[31])              \
        : "r"(tmem_addr))

// SMEM descriptor: SW128, version 1, SBO=64 (1024B per 8-row group), LBO=1
#define SMEM_DESC_BASE ((2ull << 61) | (1ull << 46) | (64ull << 32) | (1ull << 16))
#endif  // USE_TCGEN05

// ===========================================================================
// Kernel 1: centroids (bf16 out) + exact fp32 leave-one-out diag. Warp/speaker.
// ===========================================================================
__global__ void __launch_bounds__(256) centroid_kernel(const float* __restrict__ E,
                                                       float* __restrict__ out) {
    if (blockIdx.x == 0 && threadIdx.x == 0) out[0] = 0.0f;

    int warp = (blockIdx.x * blockDim.x + threadIdx.x) >> 5;
    int lane = threadIdx.x & 31;
    if (warp >= NSPK) return;

    const float* e = E + (size_t)warp * (MUTT * DEMB);

    float4 s[4];
#pragma unroll
    for (int c = 0; c < 4; c++) s[c] = make_float4(0.f, 0.f, 0.f, 0.f);

    float q[MUTT];
#pragma unroll
    for (int m = 0; m < MUTT; m++) {
        q[m] = 0.f;
#pragma unroll
        for (int c = 0; c < 4; c++) {
            float4 v = *(const float4*)(e + m * DEMB + c * 128 + lane * 4);
            s[c].x += v.x; s[c].y += v.y; s[c].z += v.z; s[c].w += v.w;
            q[m] += v.x * v.x + v.y * v.y + v.z * v.z + v.w * v.w;
        }
    }
    float p[MUTT];
#pragma unroll
    for (int m = 0; m < MUTT; m++) {
        p[m] = 0.f;
#pragma unroll
        for (int c = 0; c < 4; c++) {
            float4 v = *(const float4*)(e + m * DEMB + c * 128 + lane * 4);
            p[m] += v.x * s[c].x + v.y * s[c].y + v.z * s[c].z + v.w * s[c].w;
        }
    }
    float ns = 0.f;
#pragma unroll
    for (int c = 0; c < 4; c++)
        ns += s[c].x * s[c].x + s[c].y * s[c].y + s[c].z * s[c].z + s[c].w * s[c].w;

#pragma unroll
    for (int off = 16; off > 0; off >>= 1) {
#pragma unroll
        for (int m = 0; m < MUTT; m++) {
            p[m] += __shfl_xor_sync(0xffffffffu, p[m], off);
            q[m] += __shfl_xor_sync(0xffffffffu, q[m], off);
        }
        ns += __shfl_xor_sync(0xffffffffu, ns, off);
    }

    float inv = rsqrtf(ns);
#pragma unroll
    for (int c = 0; c < 4; c++) {
        __nv_bfloat162 h0 = __float22bfloat162_rn(make_float2(s[c].x * inv, s[c].y * inv));
        __nv_bfloat162 h1 = __float22bfloat162_rn(make_float2(s[c].z * inv, s[c].w * inv));
        uint32_t u0 = *(uint32_t*)&h0, u1 = *(uint32_t*)&h1;
        *(uint2*)(g_cent_bf + (size_t)warp * DEMB + c * 128 + lane * 4) = make_uint2(u0, u1);
    }
    if (lane < MUTT) {
        float pm = p[lane], qm = q[lane];
        g_diag[warp * MUTT + lane] = (pm - qm) * rsqrtf(ns - 2.f * pm + qm);
    }
}

// ===========================================================================
// Kernel 2 (grid 128, block 416, dynamic smem)
//   sm_103a: warp-specialized tcgen05 pipeline, N=64 chunks (32), with:
//     - cp.async B loaders (no LDG->reg->STS round trip, no LSU pressure)
//     - 4 D buffers in TMEM (issuer runs up to 4 chunks ahead; consumer
//       mma_done waits are pre-fired fast-paths)
//     warps 0-7  : pure epilogue consumers
//     warps 8-11 : B-chunk loaders (cp.async, NBUF=3 smem ring)
//     warp 12    : MMA issuer
//   TMEM: A = [0,256), D = [256+64*(c&3), ...) exactly 512 cols
//   Barriers:
//     mbar ring 4       : mma_done(c) (consumers wait c, loaders wait c-3)
//     named 3/4/5 (160) : B buffer ready, loaders arrive / issuer syncs
//     named 9..12 (288) : D[c&3] free, consumers arrive / issuer syncs (c-4)
//     named 8 (288)     : A-in-TMEM;  named 2 (256): consumer reductions
// ===========================================================================
#define BROWS 128
#define NB 64
#define NCHUNK (NSPK / NB)     // 32
#define KSTEPS (DEMB / 16)     // 32
#define NBUF 3
#define NDBUF 4
#define MMA_IDESC 0x8100490u   // f32 acc, bf16 A/B, K-major, M=128, N=64
#define NTHREADS 416
#define LOG2E 1.4426950408889634f

// shared memory offsets
#define SM_TMEMPTR 0
#define SM_MBAR0   8                      // 4 mbarriers: 8..40
#define SM_BUF0    2048
#define SM_RED     (2048 + NBUF * 65536)  // 256 floats
#define SM_WS      (SM_RED + 1024)        // 4 floats
#define SMEM_TOTAL (SM_WS + 64)

// TMEM columns
#define TM_A  0
#define TM_D0 256

__global__ void __launch_bounds__(NTHREADS, 1) gemm_loss_kernel(const float* __restrict__ E,
                                                                const float* __restrict__ wp,
                                                                const float* __restrict__ bp,
                                                                float* __restrict__ out) {
    extern __shared__ char smem[];
#if USE_TCGEN05
    uint32_t smem_base = smem_u32(smem);
    int tid = threadIdx.x;
    int wid = tid >> 5;
    int lane = tid & 31;
    int r0 = blockIdx.x * BROWS;

    if (wid == 0) TCGEN05_ALLOC(smem_base + SM_TMEMPTR, 512);
    if (tid == 0) {
#pragma unroll
        for (int i = 0; i < 4; i++) MBARRIER_INIT(smem_base + SM_MBAR0 + 8 * i, 1);
    }
    __syncthreads();
    uint32_t tmem_base;
    asm volatile("ld.shared.b32 %0, [%1];" : "=r"(tmem_base) : "r"(smem_base + SM_TMEMPTR));

    if (wid >= 8 && wid < 12) {
        // -------- loader warps (8-11): cp.async B chunks into 3-ring --------
        int ltid = tid - 256;
        int bufidx = 0;
#pragma unroll 1
        for (int c = 0; c < NCHUNK; c++) {
            if (c >= NBUF) {
                int pc = c - NBUF;   // buf free once MMA(pc) consumed it
                MBARRIER_WAIT_PARITY(smem_base + SM_MBAR0 + 8 * (pc & 3), (pc >> 2) & 1);
            }
            const char* g = (const char*)(g_cent_bf + (size_t)c * NB * DEMB);
            uint32_t buf = smem_base + SM_BUF0 + bufidx * 65536;
#pragma unroll
            for (int i = 0; i < 32; i++) {
                int lin = ltid + i * 128;            // 16B unit, 0..4095
                int brow = lin >> 6;                 // centroid row in chunk
                int kc = (lin & 63) << 3;            // bf16 k-col, multiple of 8
                uint32_t off = (uint32_t)((brow >> 3) + ((kc >> 6) << 3)) * 1024u
                             + (uint32_t)(brow & 7) * 128u + (uint32_t)(kc & 63) * 2u;
                off ^= ((off >> 3) & 0x70u);         // SW128 swizzle
                CP_ASYNC_16(buf + off, g + (size_t)lin * 16);
            }
            CP_ASYNC_COMMIT();
            CP_ASYNC_WAIT_ALL();
            FENCE_PROXY_ASYNC();
            {
                int barid = 3 + bufidx;
                asm volatile("bar.arrive %0, 160;" :: "r"(barid) : "memory");
            }
            bufidx = (bufidx + 1 == NBUF) ? 0 : bufidx + 1;
        }
    } else if (wid == 12) {
        // ------------------------ MMA issuer warp (12) ------------------------
        asm volatile("bar.sync 8, 288;" ::: "memory");  // A in TMEM
        TCGEN05_FENCE_AFTER();
        int bufidx = 0;
#pragma unroll 1
        for (int c = 0; c < NCHUNK; c++) {
            {   // B buffer ready
                int barid = 3 + bufidx;
                asm volatile("bar.sync %0, 160;" :: "r"(barid) : "memory");
            }
            if (c >= NDBUF) {   // D[c&3] free (epi(c-4) done)
                int barid = 9 + (c & 3);
                asm volatile("bar.sync %0, 288;" :: "r"(barid) : "memory");
            }
            if (elect_one()) {
                uint64_t bdesc = SMEM_DESC_BASE |
                    (((uint64_t)(smem_base + SM_BUF0 + bufidx * 65536) >> 4) & 0x3FFF);
                uint32_t dt = tmem_base + TM_D0 + (c & 3) * 64;
#pragma unroll
                for (int s = 0; s < KSTEPS; s++) {
                    uint64_t bd = bdesc + (uint64_t)(((s >> 2) << 9) + ((s & 3) << 1));
                    TCGEN05_MMA_F16(dt, tmem_base + TM_A + s * 8, bd, MMA_IDESC, s > 0);
                }
                TCGEN05_COMMIT(smem_base + SM_MBAR0 + 8 * (c & 3));
            }
            bufidx = (bufidx + 1 == NBUF) ? 0 : bufidx + 1;
        }
    } else {
        // ---------------- consumer warps (0-7): pure epilogue ----------------
        // Prologue: A (f32 -> bf16) into TMEM, threads 0-127 own one row each
        if (tid < 128) {
            const float* arow = E + (size_t)(r0 + tid) * DEMB;
            uint32_t warp_off = (uint32_t)(tid >> 5) << 21;
#pragma unroll 1
            for (int bt = 0; bt < 4; bt++) {
                uint32_t regs[64];
#pragma unroll
                for (int i = 0; i < 32; i++) {
                    float4 v = ((const float4*)(arow + bt * 128))[i];
                    __nv_bfloat162 h0 = __float22bfloat162_rn(make_float2(v.x, v.y));
                    __nv_bfloat162 h1 = __float22bfloat162_rn(make_float2(v.z, v.w));
                    regs[2 * i]     = *(uint32_t*)&h0;
                    regs[2 * i + 1] = *(uint32_t*)&h1;
                }
                TCGEN05_ST_X64(tmem_base + TM_A + bt * 64 + warp_off, regs);
            }
            TCGEN05_WAIT_ST();
        }
        TCGEN05_FENCE_BEFORE();
        asm volatile("bar.arrive 8, 288;" ::: "memory");  // A ready -> issuer

        float wabs = fabsf(wp[0]);
        float bb = bp[0];
        float wl = wabs * LOG2E;
        float bl = bb * LOG2E;
        int half = wid >> 2;                   // 0: cols 0-31, 1: cols 32-63
        int myrow = ((wid & 3) << 5) + lane;   // TMEM lane = A-tile row
        int grow = r0 + myrow;
        int spk = grow >> 3;                   // own-speaker column (M=8)
        float dval = fmaf(wabs, g_diag[grow], bb);   // exact, natural-log domain
        float dval_l = dval * LOG2E;
        float e_dval = ex2f(dval_l);
        float ssum = 0.f;

#pragma unroll 1
        for (int c = 0; c < NCHUNK; c++) {
            MBARRIER_WAIT_PARITY(smem_base + SM_MBAR0 + 8 * (c & 3), (c >> 2) & 1);
            TCGEN05_FENCE_AFTER();
            uint32_t d[32];
            TCGEN05_LD_X32(d, tmem_base + TM_D0 + (c & 3) * 64 + half * 32);
            TCGEN05_WAIT_LD();
            int colbase = c * NB + half * 32;
            float s0 = 0.f, s1 = 0.f;
#pragma unroll
            for (int j = 0; j < 32; j += 2) {
                s0 += ex2f(fmaf(wl, __uint_as_float(d[j]), bl));
                s1 += ex2f(fmaf(wl, __uint_as_float(d[j + 1]), bl));
            }
            int dsel = spk - colbase;
            if (dsel >= 0 && dsel < 32) {   // replace own column by exact diag
                s0 += e_dval - ex2f(fmaf(wl, __uint_as_float(d[dsel]), bl));
            }
            ssum += s0 + s1;
            TCGEN05_FENCE_BEFORE();
            {   // D[c&3] free -> issuer may reuse for chunk c+4
                int barid = 9 + (c & 3);
                asm volatile("bar.arrive %0, 288;" :: "r"(barid) : "memory");
            }
        }

        // combine halves, per-row loss, block reduce (consumer-only barrier 2)
        float* red = (float*)(smem + SM_RED);
        red[half * 128 + myrow] = ssum;
        asm volatile("bar.sync 2, 256;" ::: "memory");

        if (wid < 4) {
            float total = red[myrow] + red[128 + myrow];
            float lr = logf(total) - dval;          // logsumexp - own logit
#pragma unroll
            for (int off = 16; off > 0; off >>= 1)
                lr += __shfl_xor_sync(0xffffffffu, lr, off);
            if (lane == 0) ((float*)(smem + SM_WS))[wid] = lr;
        }
        asm volatile("bar.sync 2, 256;" ::: "memory");
        if (tid == 0) {
            float* ws = (float*)(smem + SM_WS);
            atomicAdd(out, (ws[0] + ws[1] + ws[2] + ws[3]) * (1.0f / (float)NMROWS));
        }
    }

    // full-CTA teardown
    __syncthreads();
    if (tid == 0) {
#pragma unroll
        for (int i = 0; i < 4; i++) MBARRIER_INVAL(smem_base + SM_MBAR0 + 8 * i);
    }
    __syncthreads();
    if (wid == 0) {
        TCGEN05_RELINQUISH();
        TCGEN05_DEALLOC(tmem_base, 512);
    }
#else
    // ---------------- portable SIMT fallback (compile-only on GB300) ----------
    float (*As)[132] = (float (*)[132])(smem);                 // [16][132]
    float (*Bs)[132] = (float (*)[132])(smem + 16 * 132 * 4);  // [16][132]
    float* red = (float*)(smem + 2 * 16 * 132 * 4);            // [16]

    int tid = threadIdx.x;
    int tx = tid & 15;
    int ty = tid >> 4;
    int r0 = blockIdx.x * BROWS;
    int rowbase = r0 + ty * 8;
    bool active = tid < 256;

    float wabs = fabsf(wp[0]);
    float bb = bp[0];

    float dval[8];
#pragma unroll
    for (int i = 0; i < 8; i++)
        dval[i] = active ? fmaf(wabs, g_diag[rowbase + i], bb) : 0.f;

    float mrun[8], srun[8];
#pragma unroll
    for (int i = 0; i < 8; i++) { mrun[i] = -1e30f; srun[i] = 0.f; }

    for (int c0 = 0; c0 < NSPK; c0 += 128) {
        float acc[8][8];
#pragma unroll
        for (int i = 0; i < 8; i++)
#pragma unroll
            for (int j = 0; j < 8; j++) acc[i][j] = 0.f;

        for (int k0 = 0; k0 < DEMB; k0 += 16) {
            for (int i4 = tid; i4 < 512; i4 += NTHREADS) {
                int row = i4 >> 2;
                int c4 = i4 & 3;
                float4 va = *(const float4*)(E + (size_t)(r0 + row) * DEMB + k0 + c4 * 4);
                As[c4 * 4 + 0][row] = va.x;
                As[c4 * 4 + 1][row] = va.y;
                As[c4 * 4 + 2][row] = va.z;
                As[c4 * 4 + 3][row] = va.w;
                uint2 ub = *(const uint2*)(g_cent_bf + (size_t)(c0 + row) * DEMB + k0 + c4 * 4);
                __nv_bfloat162 b0 = *(__nv_bfloat162*)&ub.x;
                __nv_bfloat162 b1 = *(__nv_bfloat162*)&ub.y;
                float2 f0 = __bfloat1622float2(b0);
                float2 f1 = __bfloat1622float2(b1);
                Bs[c4 * 4 + 0][row] = f0.x;
                Bs[c4 * 4 + 1][row] = f0.y;
                Bs[c4 * 4 + 2][row] = f1.x;
                Bs[c4 * 4 + 3][row] = f1.y;
            }
            __syncthreads();

            if (active) {
#pragma unroll
                for (int kk = 0; kk < 16; kk++) {
                    float4 a0 = *(const float4*)(&As[kk][ty * 8]);
                    float4 a1 = *(const float4*)(&As[kk][ty * 8 + 4]);
                    float4 b0 = *(const float4*)(&Bs[kk][tx * 8]);
                    float4 b1 = *(const float4*)(&Bs[kk][tx * 8 + 4]);
                    float av[8] = {a0.x, a0.y, a0.z, a0.w, a1.x, a1.y, a1.z, a1.w};
                    float bv[8] = {b0.x, b0.y, b0.z, b0.w, b1.x, b1.y, b1.z, b1.w};
#pragma unroll
                    for (int i = 0; i < 8; i++)
#pragma unroll
                        for (int j = 0; j < 8; j++) acc[i][j] = fmaf(av[i], bv[j], acc[i][j]);
                }
            }
            __syncthreads();
        }

        if (active) {
            int colbase = c0 + tx * 8;
#pragma unroll
            for (int i = 0; i < 8; i++) {
                int spk = (rowbase + i) >> 3;
                float z[8];
#pragma unroll
                for (int j = 0; j < 8; j++) z[j] = fmaf(wabs, acc[i][j], bb);
                int dcol = spk - colbase;
                if (dcol >= 0 && dcol < 8) z[dcol] = dval[i];

                float tm = z[0];
#pragma unroll
                for (int j = 1; j < 8; j++) tm = fmaxf(tm, z[j]);
#pragma unroll
                for (int off = 8; off > 0; off >>= 1)
                    tm = fmaxf(tm, __shfl_xor_sync(0xffffffffu, tm, off));

                float nm = fmaxf(mrun[i], tm);
                float ts = 0.f;
#pragma unroll
                for (int j = 0; j < 8; j++) ts += __expf(z[j] - nm);
#pragma unroll
                for (int off = 8; off > 0; off >>= 1)
                    ts += __shfl_xor_sync(0xffffffffu, ts, off);

                srun[i] = srun[i] * __expf(mrun[i] - nm) + ts;
                mrun[i] = nm;
            }
        }
    }

    if (active && tx == 0) {
        float lsum = 0.f;
#pragma unroll
        for (int i = 0; i < 8; i++) lsum += logf(srun[i]) + mrun[i] - dval[i];
        red[ty] = lsum;
    }
    __syncthreads();
    if (tid == 0) {
        float t = 0.f;
#pragma unroll
        for (int k = 0; k < 16; k++) t += red[k];
        atomicAdd(out, t * (1.0f / (float)NMROWS));
    }
#endif
}

// ===========================================================================
extern "C" void kernel_launch(void* const* d_in, const int* in_sizes, int n_in,
                              void* d_out, int out_size) {
    const float* E = (const float*)d_in[0];
    const float* w = (const float*)d_in[1];
    const float* b = (const float*)d_in[2];
    float* out = (float*)d_out;

    cudaFuncSetAttribute(gemm_loss_kernel,
                         cudaFuncAttributeMaxDynamicSharedMemorySize, SMEM_TOTAL);

    centroid_kernel<<<256, 256>>>(E, out);
    gemm_loss_kernel<<<NMROWS / BROWS, NTHREADS, SMEM_TOTAL>>>(E, w, b, out);
}